// round 2
// baseline (speedup 1.0000x reference)
#include <cuda_runtime.h>
#include <cuda_bf16.h>
#include <math.h>

// Problem constants
#define N_EMBED   512
#define EMBED_DIM 64
#define K_SPARSE  4
#define NSIG      16384           // 16 * 32 * 32
#define ZQ_ELEMS  1048576         // 16 * 64 * 32 * 32
#define N_BINS    33
#define WARPS_PER_BLOCK 8
#define OMP_BLOCKS (NSIG / WARPS_PER_BLOCK)   // 2048

// Scratch (device globals: no allocations allowed)
__device__ float g_DnT[N_EMBED * EMBED_DIM];     // normalized dict, atom-major [512][64]
__device__ float g_G[N_EMBED * N_EMBED];         // Gram matrix [512][512]
__device__ float g_part[OMP_BLOCKS];             // per-block loss partial sums

// ---------------------------------------------------------------------------
// Kernel 1: normalize dictionary columns. dict layout [64][512] row-major.
// Block = one column (atom), 64 threads.
__global__ void k_norm(const float* __restrict__ dict) {
    int n = blockIdx.x;
    int m = threadIdx.x;
    float v = dict[m * N_EMBED + n];
    __shared__ float sh[EMBED_DIM];
    sh[m] = v * v;
    __syncthreads();
    for (int o = 32; o > 0; o >>= 1) {
        if (m < o) sh[m] += sh[m + o];
        __syncthreads();
    }
    float nr = fmaxf(sqrtf(sh[0]), 1e-10f);
    g_DnT[n * EMBED_DIM + m] = v / nr;
}

// ---------------------------------------------------------------------------
// Kernel 2: Gram matrix G = Dn^T Dn. Block = row i, 128 threads, 4 j each.
__global__ void k_gram() {
    int i = blockIdx.x;
    __shared__ float di[EMBED_DIM];
    if (threadIdx.x < EMBED_DIM) di[threadIdx.x] = g_DnT[i * EMBED_DIM + threadIdx.x];
    __syncthreads();
    #pragma unroll
    for (int t = 0; t < 4; ++t) {
        int j = threadIdx.x + t * 128;
        const float* dj = g_DnT + j * EMBED_DIM;
        float acc = 0.f;
        #pragma unroll
        for (int m = 0; m < EMBED_DIM; ++m) acc = fmaf(di[m], dj[m], acc);
        g_G[i * N_EMBED + j] = acc;
    }
}

// ---------------------------------------------------------------------------
// Kernel 3: OMP, one warp per signal.
__global__ void __launch_bounds__(256, 2) k_omp(const float* __restrict__ z_e,
                                                float* __restrict__ out) {
    __shared__ float4 xs4[WARPS_PER_BLOCK][16];   // signal per warp (64 floats)
    __shared__ float warp_loss[WARPS_PER_BLOCK];

    int wid  = threadIdx.x >> 5;
    int lane = threadIdx.x & 31;
    int s    = blockIdx.x * WARPS_PER_BLOCK + wid;     // signal index
    int b    = s >> 10;
    int hw   = s & 1023;

    float* xs = (float*)&xs4[wid][0];

    // Load signal: component c of signal s lives at z_e[((b*64+c)<<10) + hw]
    {
        int c0 = lane * 2;
        xs[c0]     = z_e[((b * EMBED_DIM + c0) << 10) + hw];
        xs[c0 + 1] = z_e[((b * EMBED_DIM + c0 + 1) << 10) + hw];
    }
    __syncwarp();

    // h_bar = Dn^T x  -- 16 atoms per lane (atom = i*32 + lane)
    float hbar[16], h[16];
    {
        const float4* Dn4 = reinterpret_cast<const float4*>(g_DnT);
        #pragma unroll
        for (int i = 0; i < 16; ++i) {
            int a = i * 32 + lane;
            const float4* da = Dn4 + a * 16;
            float acc = 0.f;
            #pragma unroll
            for (int j = 0; j < 16; ++j) {
                float4 d  = da[j];
                float4 xv = xs4[wid][j];
                acc = fmaf(d.x, xv.x, acc);
                acc = fmaf(d.y, xv.y, acc);
                acc = fmaf(d.z, xv.z, acc);
                acc = fmaf(d.w, xv.w, acc);
            }
            hbar[i] = acc;
            h[i]    = acc;
        }
    }

    // OMP loop, fully unrolled K=4
    unsigned used = 0;
    int   sup[K_SPARSE];
    float hbs[K_SPARSE];
    float Lm[K_SPARSE][K_SPARSE];
    float coef[K_SPARSE];
    float g[3][16];   // cached G rows for first 3 selected atoms

    #pragma unroll
    for (int k = 0; k < K_SPARSE; ++k) {
        // masked argmax of |h| (reference: masked entries become 0, first-max wins)
        float bv = -1.f; int bi = 0x7fffffff; float bh = 0.f;
        #pragma unroll
        for (int i = 0; i < 16; ++i) {
            float av = ((used >> i) & 1u) ? 0.0f : fabsf(h[i]);
            int gi = i * 32 + lane;
            if (av > bv || (av == bv && gi < bi)) { bv = av; bi = gi; bh = hbar[i]; }
        }
        #pragma unroll
        for (int off = 16; off; off >>= 1) {
            float ov = __shfl_xor_sync(0xffffffffu, bv, off);
            int   oi = __shfl_xor_sync(0xffffffffu, bi, off);
            float oh = __shfl_xor_sync(0xffffffffu, bh, off);
            if (ov > bv || (ov == bv && oi < bi)) { bv = ov; bi = oi; bh = oh; }
        }
        sup[k] = bi;
        hbs[k] = bh;
        if ((bi & 31) == lane) used |= 1u << (bi >> 5);

        // incremental Cholesky of Gram submatrix (mirrors reference numerics)
        if (k == 0) {
            Lm[0][0] = 1.f;
        } else {
            float w[3]; float ss = 0.f;
            #pragma unroll
            for (int a = 0; a < k; ++a) {
                float gv = g_G[sup[a] * N_EMBED + bi];
                #pragma unroll
                for (int c = 0; c < a; ++c) gv -= Lm[a][c] * w[c];
                w[a] = gv / Lm[a][a];
                ss += w[a] * w[a];
            }
            #pragma unroll
            for (int a = 0; a < k; ++a) Lm[k][a] = w[a];
            Lm[k][k] = sqrtf(fmaxf(1.f - ss, 1e-12f));
        }

        // solve L y = hbs ; L^T coef = y  (size k+1)
        {
            float y[K_SPARSE];
            #pragma unroll
            for (int a = 0; a <= k; ++a) {
                float v = hbs[a];
                #pragma unroll
                for (int c = 0; c < a; ++c) v -= Lm[a][c] * y[c];
                y[a] = v / Lm[a][a];
            }
            #pragma unroll
            for (int a = k; a >= 0; --a) {
                float v = y[a];
                #pragma unroll
                for (int c = a + 1; c <= k; ++c) v -= Lm[c][a] * coef[c];
                coef[a] = v / Lm[a][a];
            }
        }

        // residual-correlation update (skip after last step)
        if (k < K_SPARSE - 1) {
            const float* Gr = g_G + sup[k] * N_EMBED;
            #pragma unroll
            for (int i = 0; i < 16; ++i) g[k][i] = Gr[i * 32 + lane];
            #pragma unroll
            for (int i = 0; i < 16; ++i) {
                float v = hbar[i];
                #pragma unroll
                for (int j = 0; j <= k; ++j) v -= coef[j] * g[j][i];
                h[i] = v;
            }
        }
    }

    // quantize coefficients to 33 bins on [-2, 2]
    float cq[K_SPARSE];
    int   bq[K_SPARSE];
    #pragma unroll
    for (int j = 0; j < K_SPARSE; ++j) {
        float c  = fminf(fmaxf(coef[j], -2.f), 2.f);
        int   bi = (int)rintf((c + 2.f) * 8.f);     // (c+2)/4*32, round half-even
        bi = min(max(bi, 0), N_BINS - 1);
        bq[j] = bi;
        cq[j] = -2.f + 0.125f * (float)bi;
    }

    // tokens (written as float, exactly representable)
    if (lane == 0) {
        float* tok = out + ZQ_ELEMS + 1 + (size_t)s * K_SPARSE;
        tok[0] = (float)(sup[0] * N_BINS + bq[0]);
        tok[1] = (float)(sup[1] * N_BINS + bq[1]);
        tok[2] = (float)(sup[2] * N_BINS + bq[2]);
        tok[3] = (float)(sup[3] * N_BINS + bq[3]);
    }

    // reconstruction, z_q_ste, loss contribution (2 channels per lane)
    float lsum = 0.f;
    #pragma unroll
    for (int t = 0; t < 2; ++t) {
        int c = lane * 2 + t;
        float r = 0.f;
        #pragma unroll
        for (int j = 0; j < K_SPARSE; ++j)
            r = fmaf(cq[j], g_DnT[sup[j] * EMBED_DIM + c], r);
        float ze = xs[c];
        float d  = r - ze;
        out[((b * EMBED_DIM + c) << 10) + hw] = ze + d;   // z_q_ste = z_e + (z_q - z_e)
        lsum += d * d;
    }
    // warp reduce
    #pragma unroll
    for (int off = 16; off; off >>= 1) lsum += __shfl_xor_sync(0xffffffffu, lsum, off);
    if (lane == 0) warp_loss[wid] = lsum;
    __syncthreads();
    if (threadIdx.x == 0) {
        float t = 0.f;
        #pragma unroll
        for (int w = 0; w < WARPS_PER_BLOCK; ++w) t += warp_loss[w];
        g_part[blockIdx.x] = t;
    }
}

// ---------------------------------------------------------------------------
// Kernel 4: deterministic final loss reduction.
__global__ void k_reduce(float* __restrict__ out) {
    __shared__ float sh[256];
    int t = threadIdx.x;
    float acc = 0.f;
    #pragma unroll
    for (int i = 0; i < OMP_BLOCKS / 256; ++i) acc += g_part[t + i * 256];
    sh[t] = acc;
    __syncthreads();
    for (int o = 128; o > 0; o >>= 1) {
        if (t < o) sh[t] += sh[t + o];
        __syncthreads();
    }
    if (t == 0) {
        float mse = sh[0] / (float)ZQ_ELEMS;
        out[ZQ_ELEMS] = mse + 0.25f * mse;   // dl_loss + COMMIT * e_loss (equal values)
    }
}

// ---------------------------------------------------------------------------
extern "C" void kernel_launch(void* const* d_in, const int* in_sizes, int n_in,
                              void* d_out, int out_size) {
    const float* z_e  = (const float*)d_in[0];
    const float* dict = (const float*)d_in[1];
    float* out = (float*)d_out;

    k_norm<<<N_EMBED, EMBED_DIM>>>(dict);
    k_gram<<<N_EMBED, 128>>>();
    k_omp<<<OMP_BLOCKS, 256>>>(z_e, out);
    k_reduce<<<1, 256>>>(out);
}

// round 3
// speedup vs baseline: 6.5760x; 6.5760x over previous
#include <cuda_runtime.h>
#include <cuda_bf16.h>
#include <math.h>

// Problem constants
#define N_EMBED   512
#define EMBED_DIM 64
#define K_SPARSE  4
#define NSIG      16384           // 16 * 32 * 32
#define ZQ_ELEMS  1048576         // 16 * 64 * 32 * 32
#define N_BINS    33
#define WARPS_PER_BLOCK 8
#define OMP_BLOCKS (NSIG / WARPS_PER_BLOCK)   // 2048

// Scratch (device globals: allocations are forbidden)
__device__ float g_Dn [EMBED_DIM * N_EMBED];     // normalized dict, dim-major [64][512]
__device__ float g_DnT[N_EMBED * EMBED_DIM];     // normalized dict, atom-major [512][64]
__device__ float g_G  [N_EMBED * N_EMBED];       // Gram matrix [512][512]
__device__ float g_hbar[(size_t)NSIG * N_EMBED]; // correlations [16384][512] (32 MB)
__device__ float g_part[OMP_BLOCKS];             // per-block loss partials

// ---------------------------------------------------------------------------
// Kernel 1: normalize dictionary columns. dict layout [64][512] row-major.
__global__ void k_norm(const float* __restrict__ dict) {
    int n = blockIdx.x;
    int m = threadIdx.x;
    float v = dict[m * N_EMBED + n];
    __shared__ float sh[EMBED_DIM];
    sh[m] = v * v;
    __syncthreads();
    for (int o = 32; o > 0; o >>= 1) {
        if (m < o) sh[m] += sh[m + o];
        __syncthreads();
    }
    float nr = fmaxf(sqrtf(sh[0]), 1e-10f);
    float dn = v / nr;
    g_Dn [m * N_EMBED + n]   = dn;
    g_DnT[n * EMBED_DIM + m] = dn;
}

// ---------------------------------------------------------------------------
// Kernel 2: Gram matrix G = Dn^T Dn. Block = row i, 128 threads, 4 j each.
__global__ void k_gram() {
    int i = blockIdx.x;
    __shared__ float di[EMBED_DIM];
    if (threadIdx.x < EMBED_DIM) di[threadIdx.x] = g_DnT[i * EMBED_DIM + threadIdx.x];
    __syncthreads();
    #pragma unroll
    for (int t = 0; t < 4; ++t) {
        int j = threadIdx.x + t * 128;
        const float* dj = g_DnT + j * EMBED_DIM;
        float acc = 0.f;
        #pragma unroll
        for (int m = 0; m < EMBED_DIM; ++m) acc = fmaf(di[m], dj[m], acc);
        g_G[i * N_EMBED + j] = acc;
    }
}

// ---------------------------------------------------------------------------
// Kernel 3: h_bar = Dn^T X, tiled GEMM. Tile: 128 signals x 128 atoms, K=64.
// 256 threads, 8x8 micro-tile per thread (split 4+4 to limit LDS conflicts).
__global__ void __launch_bounds__(256) k_hbar(const float* __restrict__ z_e) {
    __shared__ float Xs[EMBED_DIM][128];   // [m][sig]  32 KB
    __shared__ float Ds[EMBED_DIM][128];   // [m][atom] 32 KB

    int bsig  = blockIdx.x << 7;           // 0..16256, same image b for whole tile
    int batom = blockIdx.y << 7;           // 0, 128, 256, 384
    int b   = bsig >> 10;
    int hw0 = bsig & 1023;
    int tid = threadIdx.x;

    // Load X tile: Xs[m][j] = z_e[b*65536 + m*1024 + hw0 + j]  (contiguous in j)
    {
        const float4* src = (const float4*)(z_e + b * 65536 + hw0);
        float4* dst = (float4*)&Xs[0][0];
        #pragma unroll
        for (int r = 0; r < 8; ++r) {
            int idx = tid + r * 256;       // 2048 float4
            int m = idx >> 5, j4 = idx & 31;
            dst[idx] = src[m * 256 + j4];  // m*1024 floats
        }
    }
    // Load D tile: Ds[m][a] = g_Dn[m*512 + batom + a]
    {
        const float4* src = (const float4*)(g_Dn + batom);
        float4* dst = (float4*)&Ds[0][0];
        #pragma unroll
        for (int r = 0; r < 8; ++r) {
            int idx = tid + r * 256;
            int m = idx >> 5, a4 = idx & 31;
            dst[idx] = src[m * 128 + a4];  // m*512 floats
        }
    }
    __syncthreads();

    int tx = tid & 15, ty = tid >> 4;
    float acc[8][8];
    #pragma unroll
    for (int i = 0; i < 8; ++i)
        #pragma unroll
        for (int j = 0; j < 8; ++j) acc[i][j] = 0.f;

    #pragma unroll 8
    for (int m = 0; m < EMBED_DIM; ++m) {
        float4 x0 = *(const float4*)&Xs[m][ty * 4];
        float4 x1 = *(const float4*)&Xs[m][64 + ty * 4];
        float4 d0 = *(const float4*)&Ds[m][tx * 4];
        float4 d1 = *(const float4*)&Ds[m][64 + tx * 4];
        float xv[8] = {x0.x, x0.y, x0.z, x0.w, x1.x, x1.y, x1.z, x1.w};
        float dv[8] = {d0.x, d0.y, d0.z, d0.w, d1.x, d1.y, d1.z, d1.w};
        #pragma unroll
        for (int i = 0; i < 8; ++i)
            #pragma unroll
            for (int j = 0; j < 8; ++j)
                acc[i][j] = fmaf(xv[i], dv[j], acc[i][j]);
    }

    // Store: hbar[sig][atom], sig in {bsig+ty*4+0..3, bsig+64+ty*4+0..3}
    #pragma unroll
    for (int i = 0; i < 8; ++i) {
        int sig = bsig + ((i < 4) ? (ty * 4 + i) : (64 + ty * 4 + i - 4));
        float* row = g_hbar + (size_t)sig * N_EMBED + batom;
        *(float4*)(row + tx * 4)      = make_float4(acc[i][0], acc[i][1], acc[i][2], acc[i][3]);
        *(float4*)(row + 64 + tx * 4) = make_float4(acc[i][4], acc[i][5], acc[i][6], acc[i][7]);
    }
}

// ---------------------------------------------------------------------------
// Kernel 4: OMP, one warp per signal. Lane owns atoms a = q*128 + lane*4 + t.
__global__ void __launch_bounds__(256, 2) k_omp(const float* __restrict__ z_e,
                                                float* __restrict__ out) {
    __shared__ float warp_loss[WARPS_PER_BLOCK];

    int wid  = threadIdx.x >> 5;
    int lane = threadIdx.x & 31;
    int s    = blockIdx.x * WARPS_PER_BLOCK + wid;
    int b    = s >> 10;
    int hw   = s & 1023;

    // Load correlations (coalesced float4)
    float4 hb[4], h[4];
    {
        const float4* hb4 = (const float4*)(g_hbar + (size_t)s * N_EMBED);
        #pragma unroll
        for (int q = 0; q < 4; ++q) { hb[q] = hb4[q * 32 + lane]; h[q] = hb[q]; }
    }
    float* hbf = (float*)hb;
    float* hf  = (float*)h;

    unsigned used = 0;
    int   sup[K_SPARSE];
    float hbs[K_SPARSE];
    float Lm[K_SPARSE][K_SPARSE];
    float coef[K_SPARSE];

    #pragma unroll
    for (int k = 0; k < K_SPARSE; ++k) {
        // masked argmax of |h| (reference: masked -> 0, first-max wins)
        float bv = -1.f; int bi = 0x7fffffff; float bh = 0.f;
        #pragma unroll
        for (int q = 0; q < 4; ++q) {
            #pragma unroll
            for (int t = 0; t < 4; ++t) {
                int li = q * 4 + t;
                float av = ((used >> li) & 1u) ? 0.0f : fabsf(hf[li]);
                int gi = q * 128 + lane * 4 + t;
                if (av > bv || (av == bv && gi < bi)) { bv = av; bi = gi; bh = hbf[li]; }
            }
        }
        #pragma unroll
        for (int off = 16; off; off >>= 1) {
            float ov = __shfl_xor_sync(0xffffffffu, bv, off);
            int   oi = __shfl_xor_sync(0xffffffffu, bi, off);
            float oh = __shfl_xor_sync(0xffffffffu, bh, off);
            if (ov > bv || (ov == bv && oi < bi)) { bv = ov; bi = oi; bh = oh; }
        }
        sup[k] = bi;
        hbs[k] = bh;
        if (((bi >> 2) & 31) == lane) used |= 1u << ((((unsigned)bi >> 7) << 2) | (bi & 3));

        // incremental Cholesky (mirrors reference numerics); redundant per-lane
        if (k == 0) {
            Lm[0][0] = 1.f;
        } else {
            float w[3]; float ss = 0.f;
            #pragma unroll
            for (int a = 0; a < k; ++a) {
                float gv = g_G[sup[a] * N_EMBED + bi];
                #pragma unroll
                for (int c = 0; c < a; ++c) gv -= Lm[a][c] * w[c];
                w[a] = gv / Lm[a][a];
                ss += w[a] * w[a];
            }
            #pragma unroll
            for (int a = 0; a < k; ++a) Lm[k][a] = w[a];
            Lm[k][k] = sqrtf(fmaxf(1.f - ss, 1e-12f));
        }

        // solve L y = hbs ; L^T coef = y  (size k+1)
        {
            float y[K_SPARSE];
            #pragma unroll
            for (int a = 0; a <= k; ++a) {
                float v = hbs[a];
                #pragma unroll
                for (int c = 0; c < a; ++c) v -= Lm[a][c] * y[c];
                y[a] = v / Lm[a][a];
            }
            #pragma unroll
            for (int a = k; a >= 0; --a) {
                float v = y[a];
                #pragma unroll
                for (int c = a + 1; c <= k; ++c) v -= Lm[c][a] * coef[c];
                coef[a] = v / Lm[a][a];
            }
        }

        // residual correlations h = hbar - sum_j coef[j] * G[sup[j], :]
        if (k < K_SPARSE - 1) {
            const float4* G4 = (const float4*)g_G;
            #pragma unroll
            for (int q = 0; q < 4; ++q) {
                float4 acc = hb[q];
                #pragma unroll
                for (int j = 0; j < K_SPARSE - 1; ++j) {
                    if (j <= k) {
                        float4 gv = G4[sup[j] * (N_EMBED / 4) + q * 32 + lane];
                        acc.x -= coef[j] * gv.x;
                        acc.y -= coef[j] * gv.y;
                        acc.z -= coef[j] * gv.z;
                        acc.w -= coef[j] * gv.w;
                    }
                }
                h[q] = acc;
            }
        }
    }

    // quantize coefficients to 33 bins on [-2, 2]
    float cq[K_SPARSE];
    int   bq[K_SPARSE];
    #pragma unroll
    for (int j = 0; j < K_SPARSE; ++j) {
        float c  = fminf(fmaxf(coef[j], -2.f), 2.f);
        int   bi = (int)rintf((c + 2.f) * 8.f);
        bi = min(max(bi, 0), N_BINS - 1);
        bq[j] = bi;
        cq[j] = -2.f + 0.125f * (float)bi;
    }

    // tokens (exactly representable in fp32)
    if (lane == 0) {
        float* tok = out + ZQ_ELEMS + 1 + (size_t)s * K_SPARSE;
        #pragma unroll
        for (int j = 0; j < K_SPARSE; ++j)
            tok[j] = (float)(sup[j] * N_BINS + bq[j]);
    }

    // reconstruction, z_q_ste, loss (2 channels per lane)
    float lsum = 0.f;
    #pragma unroll
    for (int t = 0; t < 2; ++t) {
        int c = lane * 2 + t;
        float r = 0.f;
        #pragma unroll
        for (int j = 0; j < K_SPARSE; ++j)
            r = fmaf(cq[j], g_DnT[sup[j] * EMBED_DIM + c], r);
        int off = ((b * EMBED_DIM + c) << 10) + hw;
        float ze = z_e[off];
        float d  = r - ze;
        out[off] = ze + d;                 // z_q_ste
        lsum += d * d;
    }
    #pragma unroll
    for (int off = 16; off; off >>= 1) lsum += __shfl_xor_sync(0xffffffffu, lsum, off);
    if (lane == 0) warp_loss[wid] = lsum;
    __syncthreads();
    if (threadIdx.x == 0) {
        float t = 0.f;
        #pragma unroll
        for (int w = 0; w < WARPS_PER_BLOCK; ++w) t += warp_loss[w];
        g_part[blockIdx.x] = t;
    }
}

// ---------------------------------------------------------------------------
// Kernel 5: deterministic final loss reduction.
__global__ void k_reduce(float* __restrict__ out) {
    __shared__ float sh[256];
    int t = threadIdx.x;
    float acc = 0.f;
    #pragma unroll
    for (int i = 0; i < OMP_BLOCKS / 256; ++i) acc += g_part[t + i * 256];
    sh[t] = acc;
    __syncthreads();
    for (int o = 128; o > 0; o >>= 1) {
        if (t < o) sh[t] += sh[t + o];
        __syncthreads();
    }
    if (t == 0) {
        float mse = sh[0] / (float)ZQ_ELEMS;
        out[ZQ_ELEMS] = mse + 0.25f * mse;   // dl_loss + COMMIT * e_loss
    }
}

// ---------------------------------------------------------------------------
extern "C" void kernel_launch(void* const* d_in, const int* in_sizes, int n_in,
                              void* d_out, int out_size) {
    const float* z_e  = (const float*)d_in[0];
    const float* dict = (const float*)d_in[1];
    float* out = (float*)d_out;

    k_norm<<<N_EMBED, EMBED_DIM>>>(dict);
    dim3 g(NSIG / 128, N_EMBED / 128);
    k_hbar<<<g, 256>>>(z_e);
    k_gram<<<N_EMBED, 128>>>();
    k_omp<<<OMP_BLOCKS, 256>>>(z_e, out);
    k_reduce<<<1, 256>>>(out);
}

// round 6
// speedup vs baseline: 6.8638x; 1.0438x over previous
#include <cuda_runtime.h>
#include <cuda_bf16.h>
#include <math.h>

// Problem constants
#define N_EMBED   512
#define EMBED_DIM 64
#define K_SPARSE  4
#define NSIG      16384           // 16 * 32 * 32
#define ZQ_ELEMS  1048576         // 16 * 64 * 32 * 32
#define N_BINS    33
#define WARPS_PER_BLOCK 8
#define OMP_BLOCKS (NSIG / WARPS_PER_BLOCK)   // 2048

typedef unsigned long long ull;

// Scratch (device globals: allocations are forbidden)
__device__ float g_Dn [EMBED_DIM * N_EMBED];     // normalized dict, dim-major [64][512]
__device__ float g_DnT[N_EMBED * EMBED_DIM];     // normalized dict, atom-major [512][64]
__device__ float g_G  [N_EMBED * N_EMBED];       // Gram matrix [512][512]
__device__ float g_hbar[(size_t)NSIG * N_EMBED]; // correlations [16384][512] (32 MB)
__device__ float g_part[OMP_BLOCKS];             // per-block loss partials

__device__ __forceinline__ unsigned redux_max_u32(unsigned v) {
    unsigned r;
    asm("redux.sync.max.u32 %0, %1, 0xffffffff;" : "=r"(r) : "r"(v));
    return r;
}
__device__ __forceinline__ unsigned redux_min_u32(unsigned v) {
    unsigned r;
    asm("redux.sync.min.u32 %0, %1, 0xffffffff;" : "=r"(r) : "r"(v));
    return r;
}
#define FMA2(acc, a, b) \
    asm("fma.rn.f32x2 %0, %1, %2, %0;" : "+l"(acc) : "l"(a), "l"(b))

// ---------------------------------------------------------------------------
// Kernel 1: normalize dictionary columns. dict layout [64][512] row-major.
__global__ void k_norm(const float* __restrict__ dict) {
    int n = blockIdx.x;
    int m = threadIdx.x;
    float v = dict[m * N_EMBED + n];
    __shared__ float sh[EMBED_DIM];
    sh[m] = v * v;
    __syncthreads();
    for (int o = 32; o > 0; o >>= 1) {
        if (m < o) sh[m] += sh[m + o];
        __syncthreads();
    }
    float nr = fmaxf(sqrtf(sh[0]), 1e-10f);
    float dn = v / nr;
    g_Dn [m * N_EMBED + n]   = dn;
    g_DnT[n * EMBED_DIM + m] = dn;
}

// ---------------------------------------------------------------------------
// Kernel 2: Gram matrix G = Dn^T Dn. Block = row i, 128 threads, 4 j each.
__global__ void k_gram() {
    int i = blockIdx.x;
    __shared__ float di[EMBED_DIM];
    if (threadIdx.x < EMBED_DIM) di[threadIdx.x] = g_DnT[i * EMBED_DIM + threadIdx.x];
    __syncthreads();
    #pragma unroll
    for (int t = 0; t < 4; ++t) {
        int j = threadIdx.x + t * 128;
        const float* dj = g_DnT + j * EMBED_DIM;
        float acc = 0.f;
        #pragma unroll
        for (int m = 0; m < EMBED_DIM; ++m) acc = fmaf(di[m], dj[m], acc);
        g_G[i * N_EMBED + j] = acc;
    }
}

// ---------------------------------------------------------------------------
// Kernel 3: h_bar = Dn^T X, tiled GEMM with packed f32x2 FMA.
// Tile: 128 signals x 128 atoms, K=64, 256 threads.
// X tile stored DUPLICATED in smem: each value twice -> ld.shared.b64 gives a
// ready (x,x) pair (16-lane broadcast, conflict-free). Thread (tx,ty) owns
// signals ty*8..ty*8+7 and atom-pairs {tx+16j : j<4} (pair p = atoms 2p,2p+1;
// stride-16 pairs make the D LDS.64 hit all 32 banks exactly once).
#define SMEM_HBAR (EMBED_DIM * 256 * 4 + EMBED_DIM * 128 * 4)   // 96 KB
__global__ void __launch_bounds__(256) k_hbar(const float* __restrict__ z_e) {
    extern __shared__ float smem_dyn[];
    float* Xd = smem_dyn;                    // [64][256] duplicated signals
    float* Ds = smem_dyn + EMBED_DIM * 256;  // [64][128] atoms

    int bsig  = blockIdx.x << 7;
    int batom = blockIdx.y << 7;
    int b   = bsig >> 10;
    int hw0 = bsig & 1023;
    int tid = threadIdx.x;

    // Fill X (duplicated): Xd[m][2j], Xd[m][2j+1] = x[m][sig j]
    {
        const float4* src = (const float4*)(z_e + b * 65536 + hw0);
        #pragma unroll
        for (int r = 0; r < 8; ++r) {
            int idx = tid + r * 256;          // 2048 float4 reads
            int m = idx >> 5, j4 = idx & 31;
            float4 v = src[m * 256 + j4];
            float4* dst = (float4*)(Xd + m * 256 + j4 * 8);
            dst[0] = make_float4(v.x, v.x, v.y, v.y);
            dst[1] = make_float4(v.z, v.z, v.w, v.w);
        }
    }
    // Fill D: Ds[m][a] = g_Dn[m*512 + batom + a]
    {
        const float4* src = (const float4*)(g_Dn + batom);
        float4* dst = (float4*)Ds;
        #pragma unroll
        for (int r = 0; r < 8; ++r) {
            int idx = tid + r * 256;
            int m = idx >> 5, a4 = idx & 31;
            dst[idx] = src[m * 128 + a4];
        }
    }
    __syncthreads();

    int tx = tid & 15, ty = tid >> 4;
    ull acc[8][4];
    #pragma unroll
    for (int i = 0; i < 8; ++i)
        #pragma unroll
        for (int j = 0; j < 4; ++j) acc[i][j] = 0ull;

    #pragma unroll 2
    for (int m = 0; m < EMBED_DIM; ++m) {
        const ull* Xp = (const ull*)(Xd + m * 256) + ty * 8;
        const ull* Dp = (const ull*)(Ds + m * 128) + tx;
        ull xx[8], dv[4];
        #pragma unroll
        for (int i = 0; i < 8; ++i) xx[i] = Xp[i];
        #pragma unroll
        for (int j = 0; j < 4; ++j) dv[j] = Dp[16 * j];
        #pragma unroll
        for (int i = 0; i < 8; ++i)
            #pragma unroll
            for (int j = 0; j < 4; ++j)
                FMA2(acc[i][j], xx[i], dv[j]);
    }

    // Store: acc[i][j] = (hbar[sig][2p], hbar[sig][2p+1]), p = tx + 16j
    #pragma unroll
    for (int i = 0; i < 8; ++i) {
        int sig = bsig + ty * 8 + i;
        ull* row = (ull*)(g_hbar + (size_t)sig * N_EMBED + batom) + tx;
        #pragma unroll
        for (int j = 0; j < 4; ++j) row[16 * j] = acc[i][j];
    }
}

// ---------------------------------------------------------------------------
// Kernel 4: OMP, one warp per signal. Lane owns atoms a = q*128 + lane*4 + t.
// Full hbar row cached in shared (512 floats/warp); h in regs; redux argmax;
// G rows re-read from L2 (G is 1 MB, L2-resident).
__global__ void __launch_bounds__(256, 3) k_omp(const float* __restrict__ z_e,
                                                float* __restrict__ out) {
    __shared__ float sh_hbar[WARPS_PER_BLOCK][N_EMBED];      // 16 KB
    __shared__ float warp_loss[WARPS_PER_BLOCK];

    int wid  = threadIdx.x >> 5;
    int lane = threadIdx.x & 31;
    int s    = blockIdx.x * WARPS_PER_BLOCK + wid;
    int b    = s >> 10;
    int hw   = s & 1023;

    // Load correlations -> h regs + full shared hbar copy
    float4 h[4];
    {
        const float4* hb4 = (const float4*)(g_hbar + (size_t)s * N_EMBED);
        float4* dst = (float4*)sh_hbar[wid];
        #pragma unroll
        for (int q = 0; q < 4; ++q) {
            float4 v = hb4[q * 32 + lane];
            h[q] = v;
            dst[q * 32 + lane] = v;
        }
    }
    __syncwarp();
    float* hf = (float*)h;

    unsigned used = 0;
    int   sup[K_SPARSE];
    float hbs[K_SPARSE];
    float Lm[K_SPARSE][K_SPARSE];
    float coef[K_SPARSE];

    #pragma unroll
    for (int k = 0; k < K_SPARSE; ++k) {
        // ---- masked argmax of |h| (masked -> 0, first-max-index wins) ----
        float best = -1.f; int bidx = 0;
        #pragma unroll
        for (int q = 0; q < 4; ++q) {
            #pragma unroll
            for (int t = 0; t < 4; ++t) {
                int li = q * 4 + t;                      // ascending gi order
                float mv = ((used >> li) & 1u) ? 0.0f : fabsf(hf[li]);
                int gi = q * 128 + lane * 4 + t;
                if (mv > best) { best = mv; bidx = gi; }
            }
        }
        unsigned M = redux_max_u32(__float_as_uint(best));   // best >= 0 here
        unsigned cand = (__float_as_uint(best) == M) ? (unsigned)bidx : 0xffffffffu;
        int bi = (int)redux_min_u32(cand);

        sup[k] = bi;
        hbs[k] = sh_hbar[wid][bi];                       // broadcast LDS
        if (((bi >> 2) & 31) == lane)
            used |= 1u << ((((unsigned)bi >> 7) << 2) | (bi & 3));

        // ---- incremental Cholesky (scalar G from L2) ----
        if (k == 0) {
            Lm[0][0] = 1.f;
        } else {
            float w[3]; float ss = 0.f;
            #pragma unroll
            for (int a = 0; a < k; ++a) {
                float gv = g_G[sup[a] * N_EMBED + bi];
                #pragma unroll
                for (int c = 0; c < a; ++c) gv -= Lm[a][c] * w[c];
                w[a] = gv / Lm[a][a];
                ss += w[a] * w[a];
            }
            #pragma unroll
            for (int a = 0; a < k; ++a) Lm[k][a] = w[a];
            Lm[k][k] = sqrtf(fmaxf(1.f - ss, 1e-12f));
        }

        // ---- solve L y = hbs ; L^T coef = y (size k+1) ----
        {
            float y[K_SPARSE];
            #pragma unroll
            for (int a = 0; a <= k; ++a) {
                float v = hbs[a];
                #pragma unroll
                for (int c = 0; c < a; ++c) v -= Lm[a][c] * y[c];
                y[a] = v / Lm[a][a];
            }
            #pragma unroll
            for (int a = k; a >= 0; --a) {
                float v = y[a];
                #pragma unroll
                for (int c = a + 1; c <= k; ++c) v -= Lm[c][a] * coef[c];
                coef[a] = v / Lm[a][a];
            }
        }

        // ---- h = hbar - sum_{j<=k} coef[j] * G[sup[j],:] (owned segments) ----
        if (k < K_SPARSE - 1) {
            const float4* hb4 = (const float4*)sh_hbar[wid];
            #pragma unroll
            for (int q = 0; q < 4; ++q) {
                float4 acc = hb4[q * 32 + lane];
                #pragma unroll
                for (int j = 0; j < K_SPARSE - 1; ++j) {
                    if (j <= k) {
                        float4 gv = ((const float4*)(g_G + sup[j] * N_EMBED))[q * 32 + lane];
                        acc.x -= coef[j] * gv.x;
                        acc.y -= coef[j] * gv.y;
                        acc.z -= coef[j] * gv.z;
                        acc.w -= coef[j] * gv.w;
                    }
                }
                h[q] = acc;
            }
        }
    }

    // quantize coefficients to 33 bins on [-2, 2]
    float cq[K_SPARSE];
    int   bq[K_SPARSE];
    #pragma unroll
    for (int j = 0; j < K_SPARSE; ++j) {
        float c  = fminf(fmaxf(coef[j], -2.f), 2.f);
        int   bi = (int)rintf((c + 2.f) * 8.f);
        bi = min(max(bi, 0), N_BINS - 1);
        bq[j] = bi;
        cq[j] = -2.f + 0.125f * (float)bi;
    }

    // tokens (exactly representable in fp32)
    if (lane == 0) {
        float* tok = out + ZQ_ELEMS + 1 + (size_t)s * K_SPARSE;
        #pragma unroll
        for (int j = 0; j < K_SPARSE; ++j)
            tok[j] = (float)(sup[j] * N_BINS + bq[j]);
    }

    // reconstruction, z_q_ste, loss (2 channels per lane)
    float lsum = 0.f;
    #pragma unroll
    for (int t = 0; t < 2; ++t) {
        int c = lane * 2 + t;
        float r = 0.f;
        #pragma unroll
        for (int j = 0; j < K_SPARSE; ++j)
            r = fmaf(cq[j], g_DnT[sup[j] * EMBED_DIM + c], r);
        int off = ((b * EMBED_DIM + c) << 10) + hw;
        float ze = z_e[off];
        float d  = r - ze;
        out[off] = ze + d;                 // z_q_ste
        lsum += d * d;
    }
    #pragma unroll
    for (int off = 16; off; off >>= 1) lsum += __shfl_xor_sync(0xffffffffu, lsum, off);
    if (lane == 0) warp_loss[wid] = lsum;
    __syncthreads();
    if (threadIdx.x == 0) {
        float t = 0.f;
        #pragma unroll
        for (int w = 0; w < WARPS_PER_BLOCK; ++w) t += warp_loss[w];
        g_part[blockIdx.x] = t;
    }
}

// ---------------------------------------------------------------------------
// Kernel 5: deterministic final loss reduction.
__global__ void k_reduce(float* __restrict__ out) {
    __shared__ float sh[256];
    int t = threadIdx.x;
    float acc = 0.f;
    #pragma unroll
    for (int i = 0; i < OMP_BLOCKS / 256; ++i) acc += g_part[t + i * 256];
    sh[t] = acc;
    __syncthreads();
    for (int o = 128; o > 0; o >>= 1) {
        if (t < o) sh[t] += sh[t + o];
        __syncthreads();
    }
    if (t == 0) {
        float mse = sh[0] / (float)ZQ_ELEMS;
        out[ZQ_ELEMS] = mse + 0.25f * mse;   // dl_loss + COMMIT * e_loss
    }
}

// ---------------------------------------------------------------------------
extern "C" void kernel_launch(void* const* d_in, const int* in_sizes, int n_in,
                              void* d_out, int out_size) {
    const float* z_e  = (const float*)d_in[0];
    const float* dict = (const float*)d_in[1];
    float* out = (float*)d_out;

    cudaFuncSetAttribute(k_hbar, cudaFuncAttributeMaxDynamicSharedMemorySize,
                         SMEM_HBAR);

    k_norm<<<N_EMBED, EMBED_DIM>>>(dict);
    dim3 g(NSIG / 128, N_EMBED / 128);
    k_hbar<<<g, 256, SMEM_HBAR>>>(z_e);
    k_gram<<<N_EMBED, 128>>>();
    k_omp<<<OMP_BLOCKS, 256>>>(z_e, out);
    k_reduce<<<1, 256>>>(out);
}

// round 7
// speedup vs baseline: 13.6744x; 1.9922x over previous
#include <cuda_runtime.h>
#include <cuda_bf16.h>
#include <math.h>

// Problem constants
#define N_EMBED   512
#define EMBED_DIM 64
#define K_SPARSE  4
#define NSIG      16384           // 16 * 32 * 32
#define ZQ_ELEMS  1048576         // 16 * 64 * 32 * 32
#define N_BINS    33
#define WARPS_PER_BLOCK 8
#define OMP_BLOCKS (NSIG / WARPS_PER_BLOCK)   // 2048

typedef unsigned long long ull;

// Scratch (device globals: allocations are forbidden)
__device__ float g_Dn [EMBED_DIM * N_EMBED];     // normalized dict, dim-major [64][512]
__device__ float g_DnT[N_EMBED * EMBED_DIM];     // normalized dict, atom-major [512][64]
__device__ float g_G  [N_EMBED * N_EMBED];       // Gram matrix [512][512]
__device__ float g_hbar[(size_t)NSIG * N_EMBED]; // correlations [16384][512] (32 MB)
__device__ float g_part[OMP_BLOCKS];             // per-block loss partials
__device__ int   g_ctr;                          // last-block counter

__device__ __forceinline__ unsigned redux_max_u32(unsigned v) {
    unsigned r;
    asm("redux.sync.max.u32 %0, %1, 0xffffffff;" : "=r"(r) : "r"(v));
    return r;
}
__device__ __forceinline__ unsigned redux_min_u32(unsigned v) {
    unsigned r;
    asm("redux.sync.min.u32 %0, %1, 0xffffffff;" : "=r"(r) : "r"(v));
    return r;
}
#define FMA2(acc, a, b) \
    asm("fma.rn.f32x2 %0, %1, %2, %0;" : "+l"(acc) : "l"(a), "l"(b))
__device__ __forceinline__ ull pack2(float v) {
    ull r; unsigned u = __float_as_uint(v);
    asm("mov.b64 %0, {%1, %1};" : "=l"(r) : "r"(u));
    return r;
}

// ---------------------------------------------------------------------------
// Kernel 1: normalize dictionary columns; also reset last-block counter.
__global__ void k_norm(const float* __restrict__ dict) {
    if (blockIdx.x == 0 && threadIdx.x == 0) g_ctr = 0;
    int n = blockIdx.x;
    int m = threadIdx.x;
    float v = dict[m * N_EMBED + n];
    __shared__ float sh[EMBED_DIM];
    sh[m] = v * v;
    __syncthreads();
    for (int o = 32; o > 0; o >>= 1) {
        if (m < o) sh[m] += sh[m + o];
        __syncthreads();
    }
    float nr = fmaxf(sqrtf(sh[0]), 1e-10f);
    float dn = v / nr;
    g_Dn [m * N_EMBED + n]   = dn;
    g_DnT[n * EMBED_DIM + m] = dn;
}

// ---------------------------------------------------------------------------
// Kernel 2: h_bar = Dn^T X. Tile: 64 signals x 128 atoms, K=64, 256 threads.
// f32x2 packed FMA; micro-tile 4 signals x 4 atom-pairs (8 atoms).
// Thread (tx,ty): tx in [0,16) owns atom-pairs {tx+16j}, ty in [0,16) owns
// signals ty*4..ty*4+3. D LDS.64: 16 lanes x 8B contiguous = all 32 banks.
__global__ void __launch_bounds__(256, 4) k_hbar(const float* __restrict__ z_e) {
    __shared__ float Xs[EMBED_DIM][64];    // [m][sig]  16 KB
    __shared__ float Ds[EMBED_DIM][128];   // [m][atom] 32 KB

    int bsig  = blockIdx.x << 6;           // 64 signals per block
    int batom = blockIdx.y << 7;           // 128 atoms per block
    int b   = bsig >> 10;
    int hw0 = bsig & 1023;
    int tid = threadIdx.x;

    // X fill: Xs[m][j] = z_e[b*65536 + m*1024 + hw0 + j]; 1024 float4 total.
    {
        const float4* src = (const float4*)(z_e + b * 65536 + hw0);
        float4* dst = (float4*)&Xs[0][0];
        #pragma unroll
        for (int r = 0; r < 4; ++r) {
            int idx = tid + r * 256;
            int m = idx >> 4, j4 = idx & 15;
            dst[idx] = src[m * 256 + j4];
        }
    }
    // D fill: Ds[m][a] = g_Dn[m*512 + batom + a]; 2048 float4 total.
    {
        const float4* src = (const float4*)(g_Dn + batom);
        float4* dst = (float4*)&Ds[0][0];
        #pragma unroll
        for (int r = 0; r < 8; ++r) {
            int idx = tid + r * 256;
            int m = idx >> 5, a4 = idx & 31;
            dst[idx] = src[m * 128 + a4];
        }
    }
    __syncthreads();

    int tx = tid & 15, ty = tid >> 4;
    ull acc[4][4];
    #pragma unroll
    for (int i = 0; i < 4; ++i)
        #pragma unroll
        for (int j = 0; j < 4; ++j) acc[i][j] = 0ull;

    #pragma unroll 4
    for (int m = 0; m < EMBED_DIM; ++m) {
        float4 xv = *(const float4*)&Xs[m][ty * 4];
        ull xx[4] = {pack2(xv.x), pack2(xv.y), pack2(xv.z), pack2(xv.w)};
        const ull* Dp = (const ull*)&Ds[m][0] + tx;
        ull dv[4];
        #pragma unroll
        for (int j = 0; j < 4; ++j) dv[j] = Dp[16 * j];
        #pragma unroll
        for (int i = 0; i < 4; ++i)
            #pragma unroll
            for (int j = 0; j < 4; ++j)
                FMA2(acc[i][j], xx[i], dv[j]);
    }

    // Store: acc[i][j] = (hbar[sig][2p], hbar[sig][2p+1]), p = tx + 16j
    #pragma unroll
    for (int i = 0; i < 4; ++i) {
        int sig = bsig + ty * 4 + i;
        ull* row = (ull*)(g_hbar + (size_t)sig * N_EMBED + batom) + tx;
        #pragma unroll
        for (int j = 0; j < 4; ++j) row[16 * j] = acc[i][j];
    }
}

// ---------------------------------------------------------------------------
// Kernel 3: Gram matrix G = Dn^T Dn, coalesced loads from g_Dn.
__global__ void k_gram() {
    int i = blockIdx.x;
    __shared__ float di[EMBED_DIM];
    if (threadIdx.x < EMBED_DIM) di[threadIdx.x] = g_DnT[i * EMBED_DIM + threadIdx.x];
    __syncthreads();
    float acc[4] = {0.f, 0.f, 0.f, 0.f};
    #pragma unroll 8
    for (int m = 0; m < EMBED_DIM; ++m) {
        float dm = di[m];
        const float* row = g_Dn + m * N_EMBED + threadIdx.x;
        #pragma unroll
        for (int t = 0; t < 4; ++t)
            acc[t] = fmaf(dm, row[t * 128], acc[t]);
    }
    #pragma unroll
    for (int t = 0; t < 4; ++t)
        g_G[i * N_EMBED + threadIdx.x + t * 128] = acc[t];
}

// ---------------------------------------------------------------------------
// Kernel 4: OMP, one warp per signal; fused deterministic loss reduction.
__global__ void __launch_bounds__(256, 3) k_omp(const float* __restrict__ z_e,
                                                float* __restrict__ out) {
    __shared__ float sh_hbar[WARPS_PER_BLOCK][N_EMBED];      // 16 KB
    __shared__ float warp_loss[WARPS_PER_BLOCK];
    __shared__ int   sh_last;

    int wid  = threadIdx.x >> 5;
    int lane = threadIdx.x & 31;
    int s    = blockIdx.x * WARPS_PER_BLOCK + wid;
    int b    = s >> 10;
    int hw   = s & 1023;

    // Load correlations -> h regs + full shared hbar copy
    float4 h[4];
    {
        const float4* hb4 = (const float4*)(g_hbar + (size_t)s * N_EMBED);
        float4* dst = (float4*)sh_hbar[wid];
        #pragma unroll
        for (int q = 0; q < 4; ++q) {
            float4 v = hb4[q * 32 + lane];
            h[q] = v;
            dst[q * 32 + lane] = v;
        }
    }
    __syncwarp();
    float* hf = (float*)h;

    unsigned used = 0;
    int   sup[K_SPARSE];
    float hbs[K_SPARSE];
    float Lm[K_SPARSE][K_SPARSE];
    float coef[K_SPARSE];

    #pragma unroll
    for (int k = 0; k < K_SPARSE; ++k) {
        // masked argmax of |h| (masked -> 0, first-max-index wins)
        float best = -1.f; int bidx = 0;
        #pragma unroll
        for (int q = 0; q < 4; ++q) {
            #pragma unroll
            for (int t = 0; t < 4; ++t) {
                int li = q * 4 + t;                      // ascending gi order
                float mv = ((used >> li) & 1u) ? 0.0f : fabsf(hf[li]);
                int gi = q * 128 + lane * 4 + t;
                if (mv > best) { best = mv; bidx = gi; }
            }
        }
        unsigned M = redux_max_u32(__float_as_uint(best));
        unsigned cand = (__float_as_uint(best) == M) ? (unsigned)bidx : 0xffffffffu;
        int bi = (int)redux_min_u32(cand);

        sup[k] = bi;
        hbs[k] = sh_hbar[wid][bi];
        if (((bi >> 2) & 31) == lane)
            used |= 1u << ((((unsigned)bi >> 7) << 2) | (bi & 3));

        // incremental Cholesky (scalar G from L2)
        if (k == 0) {
            Lm[0][0] = 1.f;
        } else {
            float w[3]; float ss = 0.f;
            #pragma unroll
            for (int a = 0; a < k; ++a) {
                float gv = g_G[sup[a] * N_EMBED + bi];
                #pragma unroll
                for (int c = 0; c < a; ++c) gv -= Lm[a][c] * w[c];
                w[a] = gv / Lm[a][a];
                ss += w[a] * w[a];
            }
            #pragma unroll
            for (int a = 0; a < k; ++a) Lm[k][a] = w[a];
            Lm[k][k] = sqrtf(fmaxf(1.f - ss, 1e-12f));
        }

        // solve L y = hbs ; L^T coef = y (size k+1)
        {
            float y[K_SPARSE];
            #pragma unroll
            for (int a = 0; a <= k; ++a) {
                float v = hbs[a];
                #pragma unroll
                for (int c = 0; c < a; ++c) v -= Lm[a][c] * y[c];
                y[a] = v / Lm[a][a];
            }
            #pragma unroll
            for (int a = k; a >= 0; --a) {
                float v = y[a];
                #pragma unroll
                for (int c = a + 1; c <= k; ++c) v -= Lm[c][a] * coef[c];
                coef[a] = v / Lm[a][a];
            }
        }

        // h = hbar - sum_{j<=k} coef[j] * G[sup[j],:]
        if (k < K_SPARSE - 1) {
            const float4* hb4 = (const float4*)sh_hbar[wid];
            #pragma unroll
            for (int q = 0; q < 4; ++q) {
                float4 acc = hb4[q * 32 + lane];
                #pragma unroll
                for (int j = 0; j < K_SPARSE - 1; ++j) {
                    if (j <= k) {
                        float4 gv = ((const float4*)(g_G + sup[j] * N_EMBED))[q * 32 + lane];
                        acc.x -= coef[j] * gv.x;
                        acc.y -= coef[j] * gv.y;
                        acc.z -= coef[j] * gv.z;
                        acc.w -= coef[j] * gv.w;
                    }
                }
                h[q] = acc;
            }
        }
    }

    // quantize coefficients to 33 bins on [-2, 2]
    float cq[K_SPARSE];
    int   bq[K_SPARSE];
    #pragma unroll
    for (int j = 0; j < K_SPARSE; ++j) {
        float c  = fminf(fmaxf(coef[j], -2.f), 2.f);
        int   bi = (int)rintf((c + 2.f) * 8.f);
        bi = min(max(bi, 0), N_BINS - 1);
        bq[j] = bi;
        cq[j] = -2.f + 0.125f * (float)bi;
    }

    // tokens (exactly representable in fp32)
    if (lane == 0) {
        float* tok = out + ZQ_ELEMS + 1 + (size_t)s * K_SPARSE;
        #pragma unroll
        for (int j = 0; j < K_SPARSE; ++j)
            tok[j] = (float)(sup[j] * N_BINS + bq[j]);
    }

    // reconstruction, z_q_ste, loss (2 channels per lane)
    float lsum = 0.f;
    #pragma unroll
    for (int t = 0; t < 2; ++t) {
        int c = lane * 2 + t;
        float r = 0.f;
        #pragma unroll
        for (int j = 0; j < K_SPARSE; ++j)
            r = fmaf(cq[j], g_DnT[sup[j] * EMBED_DIM + c], r);
        int off = ((b * EMBED_DIM + c) << 10) + hw;
        float ze = z_e[off];
        float d  = r - ze;
        out[off] = ze + d;                 // z_q_ste
        lsum += d * d;
    }
    #pragma unroll
    for (int off = 16; off; off >>= 1) lsum += __shfl_xor_sync(0xffffffffu, lsum, off);
    if (lane == 0) warp_loss[wid] = lsum;
    __syncthreads();

    // per-block partial + last-block detection
    if (threadIdx.x == 0) {
        float t = 0.f;
        #pragma unroll
        for (int w = 0; w < WARPS_PER_BLOCK; ++w) t += warp_loss[w];
        g_part[blockIdx.x] = t;
        __threadfence();
        int old = atomicAdd(&g_ctr, 1);
        sh_last = (old == OMP_BLOCKS - 1) ? 1 : 0;
    }
    __syncthreads();

    // last block: deterministic fixed-order final reduction
    if (sh_last) {
        float* red = sh_hbar[0];          // reuse smem
        int t = threadIdx.x;
        float acc = 0.f;
        #pragma unroll
        for (int i = 0; i < OMP_BLOCKS / 256; ++i) acc += g_part[t + i * 256];
        red[t] = acc;
        __syncthreads();
        for (int o = 128; o > 0; o >>= 1) {
            if (t < o) red[t] += red[t + o];
            __syncthreads();
        }
        if (t == 0) {
            float mse = red[0] / (float)ZQ_ELEMS;
            out[ZQ_ELEMS] = mse + 0.25f * mse;   // dl_loss + COMMIT * e_loss
        }
    }
}

// ---------------------------------------------------------------------------
extern "C" void kernel_launch(void* const* d_in, const int* in_sizes, int n_in,
                              void* d_out, int out_size) {
    const float* z_e  = (const float*)d_in[0];
    const float* dict = (const float*)d_in[1];
    float* out = (float*)d_out;

    k_norm<<<N_EMBED, EMBED_DIM>>>(dict);
    dim3 g(NSIG / 64, N_EMBED / 128);
    k_hbar<<<g, 256>>>(z_e);
    k_gram<<<N_EMBED, 128>>>();
    k_omp<<<OMP_BLOCKS, 256>>>(z_e, out);
}